// round 17
// baseline (speedup 1.0000x reference)
#include <cuda_runtime.h>
#include <cuda_bf16.h>
#include <cstdint>

// RAPiD decode:
//   raw:    (nB=64, nA*6=18, nH=128, nW=128) fp32, channel-major
//   out:    (nB, nA*nH*nW, 6) fp32
//
// R17 = R16 (confirmed best, 24.61us: 2px/thread LDG.64 channel loads with
// frac-0.5 evict_last input policy, tanh transcendentals, warp-private smem
// transpose staging, coalesced STG.128 drain with evict_last output policy)
// + .L2::256B prefetch promotion on the channel loads.
// Rationale: profile is latency-exposure bound (DRAM 56 / L1 57 / issue 41,
// occ 83 -- nothing saturated). Each warp reads one 256B segment per channel
// and the adjacent warp reads the next segment: 256B promotion makes every
// miss prefetch its sequential neighbor, converting ~half the DRAM-latency
// misses into L2 hits at zero instruction/register/traffic cost.

namespace {
constexpr int nB = 64;
constexpr int nA = 3;
constexpr int nH = 128;
constexpr int nW = 128;
constexpr int HW = nH * nW;              // 16384 pixels per (b,a) slice
constexpr int WARPS_PER_BLOCK = 8;
constexpr int PIX_PER_WARP = 64;         // 2 per lane
constexpr int PIX_PER_BLOCK = WARPS_PER_BLOCK * PIX_PER_WARP;  // 512
constexpr int BLOCKS_PER_SLICE = HW / PIX_PER_BLOCK;           // 32
}

// sigmoid(x) = 0.5 + 0.5*tanh(0.5x)  -- one MUFU.TANH
__device__ __forceinline__ float tanh_half(float x) {
    float t;
    asm("tanh.approx.f32 %0, %1;" : "=f"(t) : "f"(x * 0.5f));
    return t;    // = tanh(x/2) = 2*sigmoid(x)-1
}

// input: pin half the lines, stream the rest (best measured mix)
__device__ __forceinline__ uint64_t mk_policy_in() {
    uint64_t pol;
    asm("createpolicy.fractional.L2::evict_last.L2::evict_first.b64 %0, 0.5;"
        : "=l"(pol));
    return pol;
}

// output: evict_last (== normal without carve-out; best of store variants)
__device__ __forceinline__ uint64_t mk_policy_out() {
    uint64_t pol;
    asm("createpolicy.fractional.L2::evict_last.b64 %0, 1.0;" : "=l"(pol));
    return pol;
}

// channel load: cache-hint policy + 256B L2 prefetch promotion
__device__ __forceinline__ float2 ldg_hint(const float* p, uint64_t pol) {
    float2 v;
    asm("ld.global.nc.L2::cache_hint.L2::256B.v2.f32 {%0, %1}, [%2], %3;"
        : "=f"(v.x), "=f"(v.y) : "l"(p), "l"(pol));
    return v;
}

__device__ __forceinline__ void stg_hint(float4* p, float4 v, uint64_t pol) {
    asm volatile("st.global.L2::cache_hint.v4.f32 [%0], {%1, %2, %3, %4}, %5;"
                 :: "l"(p), "f"(v.x), "f"(v.y), "f"(v.z), "f"(v.w), "l"(pol)
                 : "memory");
}

__global__ void __launch_bounds__(256)
rapid_decode_kernel(const float* __restrict__ raw,
                    const float* __restrict__ anchors,
                    const int* __restrict__ img_h_p,
                    const int* __restrict__ img_w_p,
                    float* __restrict__ out)
{
    __shared__ float stage[WARPS_PER_BLOCK * PIX_PER_WARP * 6];

    const int tid  = threadIdx.x;
    const int lane = tid & 31;
    const int warp = tid >> 5;

    const int slice   = blockIdx.x >> 5;                     // / BLOCKS_PER_SLICE
    const int blk_in  = blockIdx.x & (BLOCKS_PER_SLICE - 1);
    const int b = slice / nA;
    const int a = slice - b * nA;

    const int warp_hw = blk_in * PIX_PER_BLOCK + warp * PIX_PER_WARP;
    const int hw0 = warp_hw + 2 * lane;                      // even
    const int h   = hw0 >> 7;                                // / nW
    const int w0  = hw0 & (nW - 1);

    const uint64_t pol_in  = mk_policy_in();
    const uint64_t pol_out = mk_policy_out();

    const float img_h = img_h_p ? (float)__ldg(img_h_p) : 1024.0f;
    const float img_w = img_w_p ? (float)__ldg(img_w_p) : 1024.0f;
    const float sx  = img_w * (1.0f / (float)nW);
    const float sy  = img_h * (1.0f / (float)nH);
    const float hsx = 0.5f * sx;
    const float hsy = 0.5f * sy;

    const float aw = __ldg(&anchors[a * 2 + 0]);
    const float ah = __ldg(&anchors[a * 2 + 1]);

    // channel base: raw[(b*18 + a*6 + c)*HW + hw0] -- coalesced LDG.64/channel
    const float* base = raw + ((size_t)(b * (nA * 6) + a * 6) * HW + hw0);
    const float2 rx = ldg_hint(base + 0 * HW, pol_in);
    const float2 ry = ldg_hint(base + 1 * HW, pol_in);
    const float2 rw = ldg_hint(base + 2 * HW, pol_in);
    const float2 rh = ldg_hint(base + 3 * HW, pol_in);
    const float2 ra = ldg_hint(base + 4 * HW, pol_in);
    const float2 rc = ldg_hint(base + 5 * HW, pol_in);

    const float cy  = ((float)h + 0.5f) * sy;
    const float cx0 = ((float)w0 + 0.5f) * sx;
    const float cx1 = ((float)w0 + 1.5f) * sx;

    // pixel 0: sigmoid(x) = 0.5 + 0.5*tanh(x/2)
    const float px0 = fmaf(tanh_half(rx.x), hsx, cx0);
    const float py0 = fmaf(tanh_half(ry.x), hsy, cy);
    const float pw0 = __expf(rw.x) * aw;
    const float ph0 = __expf(rh.x) * ah;
    const float pa0 = tanh_half(ra.x) * 180.0f;             // 360*sig-180
    const float pc0 = fmaf(tanh_half(rc.x), 0.5f, 0.5f);
    // pixel 1
    const float px1 = fmaf(tanh_half(rx.y), hsx, cx1);
    const float py1 = fmaf(tanh_half(ry.y), hsy, cy);
    const float pw1 = __expf(rw.y) * aw;
    const float ph1 = __expf(rh.y) * ah;
    const float pa1 = tanh_half(ra.y) * 180.0f;
    const float pc1 = fmaf(tanh_half(rc.y), 0.5f, 0.5f);

    // stage into warp-private smem: 48B/lane stride, conflict-free per phase
    float4* ws = (float4*)(stage + warp * (PIX_PER_WARP * 6));
    ws[3 * lane + 0] = make_float4(px0, py0, pw0, ph0);
    ws[3 * lane + 1] = make_float4(pa0, pc0, px1, py1);
    ws[3 * lane + 2] = make_float4(pw1, ph1, pa1, pc1);

    __syncwarp();

    // drain: warp's output region is 1536B contiguous -> 3 coalesced STG.128
    float4* og = (float4*)(out + ((size_t)slice * HW + warp_hw) * 6);
    stg_hint(og + lane +  0, ws[lane +  0], pol_out);
    stg_hint(og + lane + 32, ws[lane + 32], pol_out);
    stg_hint(og + lane + 64, ws[lane + 64], pol_out);
}

extern "C" void kernel_launch(void* const* d_in, const int* in_sizes, int n_in,
                              void* d_out, int out_size)
{
    const float* raw     = (const float*)d_in[0];
    const float* anchors = (const float*)d_in[1];
    const int* img_h_p   = (n_in > 2) ? (const int*)d_in[2] : nullptr;
    const int* img_w_p   = (n_in > 3) ? (const int*)d_in[3] : nullptr;
    float* out = (float*)d_out;

    const int grid = nB * nA * BLOCKS_PER_SLICE;   // 6144 blocks
    rapid_decode_kernel<<<grid, 256>>>(raw, anchors, img_h_p, img_w_p, out);
}